// round 14
// baseline (speedup 1.0000x reference)
#include <cuda_runtime.h>
#include <cuda_bf16.h>
#include <math.h>

// ---------------- problem constants ----------------
#define NN      65536
#define ROWS    16      // BATCH*CH
#define JLEV    5
#define QQ      8
#define CQ      32      // QQ*CH
#define TT      15
#define OUTN    16384   // NN/4
#define OUTCH   160     // JLEV*CQ

typedef unsigned long long ull;

// ---------------- wavelet filters ----------------
__constant__ float c_H0O[13] = {
  -0.00455690456024f, -0.00543947593727f,  0.01702522388155f,  0.02382538479492f,
  -0.10671180468666f,  0.01186609203379f,  0.56881042071212f,  0.75614564389252f,
   0.27529538466888f, -0.11720388769911f, -0.03887280126882f,  0.03466034684485f,
  -0.00388321199915f };
__constant__ float c_H1O[13] = {
  -0.00388321199915f, -0.03466034684485f, -0.03887280126882f,  0.11720388769911f,
   0.27529538466888f, -0.75614564389252f,  0.56881042071212f, -0.01186609203379f,
  -0.10671180468666f, -0.02382538479492f,  0.01702522388155f,  0.00543947593727f,
  -0.00455690456024f };
__constant__ float c_H0A[10] = {
   0.03516384f, 0.0f, -0.08832942f, 0.23389032f, 0.76027237f,
   0.58751830f, 0.0f, -0.11430184f, 0.0f, 0.0f };
__constant__ float c_H0B[10] = {
   0.0f, 0.0f, -0.11430184f, 0.0f, 0.58751830f,
   0.76027237f, 0.23389032f, -0.08832942f, 0.0f, 0.03516384f };
__constant__ float c_H1A[10] = {
   0.0f, 0.0f, -0.11430184f, 0.0f, 0.58751830f,
  -0.76027237f, 0.23389032f, 0.08832942f, 0.0f, -0.03516384f };
__constant__ float c_H1B[10] = {
  -0.03516384f, 0.0f, 0.08832942f, 0.23389032f, -0.76027237f,
   0.58751830f, 0.0f, -0.11430184f, 0.0f, 0.0f };

// ---------------- scratch: interleaved (r,i) bandpass ----------------
__device__ float2 g_bp[(size_t)JLEV * ROWS * NN];

// ---------------- packed helpers / fast math ----------------
__device__ __forceinline__ ull pack2(float x, float y) {
  ull r; asm("mov.b64 %0, {%1, %2};" : "=l"(r) : "f"(x), "f"(y)); return r;
}
__device__ __forceinline__ void unpack2(ull v, float& x, float& y) {
  asm("mov.b64 {%0, %1}, %2;" : "=f"(x), "=f"(y) : "l"(v));
}
__device__ __forceinline__ ull ffma2(ull a, ull b, ull c) {
  ull d; asm("fma.rn.f32x2 %0, %1, %2, %3;" : "=l"(d) : "l"(a), "l"(b), "l"(c));
  return d;
}
__device__ __forceinline__ float fsqrt_fast(float x) {
  float r; asm("sqrt.approx.f32 %0, %1;" : "=f"(r) : "f"(x)); return r;
}
__device__ __forceinline__ float fex2_fast(float x) {
  float r; asm("ex2.approx.f32 %0, %1;" : "=f"(r) : "f"(x)); return r;
}

// ---------------- kernel 1: undecimated dual-tree CWT ----------------
#define TILE_W 2048
#define HALO   80
#define EXT    (TILE_W + 2*HALO)   // 2208

template<int D, int M>
__device__ __forceinline__ void tree_level(
    const float* la, const float* lb,
    float* la_n, float* lb_n,
    float2* __restrict__ bp)
{
  const int PAD = (D * 9) / 2;
  for (int i = threadIdx.x; i < TILE_W; i += 256) {
    const int s = HALO + i;
    float ar = 0.f, ai = 0.f;
#pragma unroll
    for (int k = 0; k < 10; k++) {
      ar = fmaf(c_H1A[k], la[s + D*k - PAD], ar);
      ai = fmaf(c_H1B[k], lb[s + D*k - PAD], ai);
    }
    bp[i] = make_float2(ar, ai);
  }
  if (la_n != nullptr) {
    for (int i = threadIdx.x; i < TILE_W + 2*M; i += 256) {
      const int s = HALO - M + i;
      float a = 0.f, b = 0.f;
#pragma unroll
      for (int k = 0; k < 10; k++) {
        a = fmaf(c_H0A[k], la[s + D*k - PAD], a);
        b = fmaf(c_H0B[k], lb[s + D*k - PAD], b);
      }
      la_n[s] = a; lb_n[s] = b;
    }
  }
}

__global__ __launch_bounds__(256) void udtcwt_kernel(const float* __restrict__ x)
{
  __shared__ float sA[EXT], sB[EXT], sC[EXT], sD[EXT];
  const int row = blockIdx.y;
  const int t0  = blockIdx.x * TILE_W;
  const float* xr = x + (size_t)row * NN;

  for (int s = threadIdx.x; s < EXT; s += 256) {
    const int g = t0 - HALO + s;
    sA[s] = (g >= 0 && g < NN) ? xr[g] : 0.f;
  }
  __syncthreads();

  {
    float2* outp = g_bp + ((size_t)(0*ROWS + row)) * NN + t0;
    for (int i = threadIdx.x; i < TILE_W; i += 256) {
      const int s = HALO + i;
      float acc = 0.f;
#pragma unroll
      for (int k = 0; k < 13; k++) acc = fmaf(c_H1O[k], sA[s + k - 6], acc);
      outp[i] = make_float2(acc, acc);
    }
    for (int i = threadIdx.x; i < TILE_W + 2*68; i += 256) {
      const int s = HALO - 68 + i;
      float acc = 0.f;
#pragma unroll
      for (int k = 0; k < 13; k++) acc = fmaf(c_H0O[k], sA[s + k - 6], acc);
      sB[s] = acc;
    }
  }
  __syncthreads();

  tree_level<1, 63>(sB, sB, sC, sD, g_bp + ((size_t)(1*ROWS + row))*NN + t0);
  __syncthreads();
  tree_level<2, 54>(sC, sD, sA, sB, g_bp + ((size_t)(2*ROWS + row))*NN + t0);
  __syncthreads();
  tree_level<4, 36>(sA, sB, sC, sD, g_bp + ((size_t)(3*ROWS + row))*NN + t0);
  __syncthreads();
  tree_level<8, 0>(sC, sD, (float*)nullptr, (float*)nullptr,
                   g_bp + ((size_t)(4*ROWS + row))*NN + t0);
}

// ---------------- kernel 2: all scales, q-amortized windows ----------------
#define TOX     256
#define ULEN    (4*TOX + 33)     // 1057
#define QSTRIDE 1088             // words per q in s_u (absorbs padded chunks)
#define BPF2    1300             // worst-case D*SPP (D=8: 8*161=1288)
#define WSTRIDE 16               // padded weights per q (16B-aligned pairs)

// word-granular swizzle matching float4-granular f^((f>>3)&7)
__device__ __forceinline__ int swzw(int i) { return i ^ (((i >> 5) & 7) << 2); }

// 15-tap packed conv on an 18-element window, weights as LDS.128 pairs
__device__ __forceinline__ void conv15(
    const ull* wq, const ull* v, ull& a0, ull& a1, ull& a2, ull& a3)
{
  const ulonglong2* wq2 = reinterpret_cast<const ulonglong2*>(wq);
  a0 = 0ull; a1 = 0ull; a2 = 0ull; a3 = 0ull;
#pragma unroll
  for (int h = 0; h < 7; h++) {           // taps 0..13 as pairs
    const ulonglong2 wp = wq2[h];
    const int k = 2 * h;
    a0 = ffma2(wp.x, v[k],     a0);
    a1 = ffma2(wp.x, v[k + 1], a1);
    a2 = ffma2(wp.x, v[k + 2], a2);
    a3 = ffma2(wp.x, v[k + 3], a3);
    a0 = ffma2(wp.y, v[k + 1], a0);
    a1 = ffma2(wp.y, v[k + 2], a1);
    a2 = ffma2(wp.y, v[k + 3], a2);
    a3 = ffma2(wp.y, v[k + 4], a3);
  }
  {                                        // tap 14 (scalar 64-bit load)
    const ull w14 = wq[14];
    a0 = ffma2(w14, v[14], a0);
    a1 = ffma2(w14, v[15], a1);
    a2 = ffma2(w14, v[16], a2);
    a3 = ffma2(w14, v[17], a3);
  }
}

template<int LD>
__device__ __forceinline__ void scatter_body(
    ull* s_bp, float* s_u, ull* s_w2, float* s_g, float* s_alpha,
    int j, int row, int o0,
    const float* __restrict__ conv_w, const float* __restrict__ roots,
    const float* __restrict__ beta_p, float* __restrict__ out)
{
  constexpr int D    = 1 << LD;
  constexpr int SU   = (ULEN + D - 1) / D;
  constexpr int CP   = (SU + 3) / 4;
  constexpr int CHK  = D * CP;
  constexpr int SLEN = 4 * CP + 18;
  constexpr int SPP  = ((SLEN + 15) & ~15) | 1;   // odd stride

  const int b = row >> 2, c = row & 3;
  const float inv_scale = exp2f(-0.5f * (float)j);
  const float beta = beta_p[0];
  const int tid  = threadIdx.x;
  const int tmin = 4 * o0 - 18;
  const int pmin = tmin - 7 * D;

  // global bp rows viewed as 64-bit words (float2 == 8B)
  const ull* bp8 = reinterpret_cast<const ull*>(
      g_bp + ((size_t)(j * ROWS + row)) * NN);

  // ---- fill phase-separated bp tile (direct 64-bit copies) ----
  for (int i = tid; i < D * SPP; i += 256) {
    const int p = i & (D - 1), s = i >> LD;
    const int idx = p * SPP + s;
    const int ii = (LD == 0) ? (idx ^ ((idx >> 4) & 3)) : idx;
    const int gi = pmin + i;
    s_bp[ii] = (gi >= 0 && gi < NN) ? bp8[gi] : 0ull;
  }
  if (tid < 37) {
    const int m = tid;
    float acc = 0.f;
    for (int k = 0; k < 13; k++) {
      const int kp = m - 2 * k;
      if (kp >= 0 && kp < 13) acc += c_H0O[k] * c_H0O[kp];
    }
    s_g[m] = acc;
  }
  // weights pre-scaled by 2^(-j/2): folds the modulus normalization into the conv
  for (int i = tid; i < QQ * WSTRIDE; i += 256) {
    const int q = i >> 4, k = i & 15;
    const float wv = (k < TT)
        ? conv_w[(size_t)(j * CQ + c * QQ + q) * TT + k] * inv_scale : 0.f;
    s_w2[i] = pack2(wv, wv);
  }
  if (tid < QQ) {
    const float rt = roots[j * CQ + c * QQ + tid];
    s_alpha[tid] = 1.f / (1.f + __expf(-rt));
  }
  __syncthreads();

  // ---- u stage: one window load serves all 8 q; deferred-store pipeline ----
  for (int m = tid; m < CHK; m += 256) {
    const int p = m & (D - 1), cc = m >> LD;
    const int base = p * SPP + 4 * cc;
    ull v[18];
#pragma unroll
    for (int t = 0; t < 18; t++) {
      const int idx = base + t;
      const int ii = (LD == 0) ? (idx ^ ((idx >> 4) & 3)) : idx;
      v[t] = s_bp[ii];                       // direct LDS.64 into pair
    }
    const int ui0 = p + ((4 * cc) << LD);
    const bool full = (tmin + ui0 >= 0) && (tmin + ui0 + (3 << LD) < NN);

    if (full) {
      // ---- hot path: pipelined — store of q-1 issues after conv of q ----
      float pu0, pu1, pu2, pu3;
      {
        ull a0, a1, a2, a3;
        conv15(s_w2, v, a0, a1, a2, a3);
        const float alpha = s_alpha[0];
        float r0, i0, r1, i1, r2, i2, r3, i3;
        unpack2(a0, r0, i0); unpack2(a1, r1, i1);
        unpack2(a2, r2, i2); unpack2(a3, r3, i3);
        pu0 = fex2_fast(alpha * __log2f(fsqrt_fast(fmaf(r0, r0, i0 * i0)) + beta));
        pu1 = fex2_fast(alpha * __log2f(fsqrt_fast(fmaf(r1, r1, i1 * i1)) + beta));
        pu2 = fex2_fast(alpha * __log2f(fsqrt_fast(fmaf(r2, r2, i2 * i2)) + beta));
        pu3 = fex2_fast(alpha * __log2f(fsqrt_fast(fmaf(r3, r3, i3 * i3)) + beta));
      }
#pragma unroll 1
      for (int q = 1; q < QQ; q++) {
        ull a0, a1, a2, a3;
        conv15(s_w2 + q * WSTRIDE, v, a0, a1, a2, a3);
        {   // deferred store of q-1 (data ready: no stall)
          float* sup = s_u + (q - 1) * QSTRIDE;
          if (LD == 0) {
            int f = ui0 >> 2; f ^= (f >> 3) & 7;
            reinterpret_cast<float4*>(sup)[f] = make_float4(pu0, pu1, pu2, pu3);
          } else {
            sup[swzw(ui0)]            = pu0;
            sup[swzw(ui0 + (1<<LD))]  = pu1;
            sup[swzw(ui0 + (2<<LD))]  = pu2;
            sup[swzw(ui0 + (3<<LD))]  = pu3;
          }
        }
        const float alpha = s_alpha[q];
        float r0, i0, r1, i1, r2, i2, r3, i3;
        unpack2(a0, r0, i0); unpack2(a1, r1, i1);
        unpack2(a2, r2, i2); unpack2(a3, r3, i3);
        pu0 = fex2_fast(alpha * __log2f(fsqrt_fast(fmaf(r0, r0, i0 * i0)) + beta));
        pu1 = fex2_fast(alpha * __log2f(fsqrt_fast(fmaf(r1, r1, i1 * i1)) + beta));
        pu2 = fex2_fast(alpha * __log2f(fsqrt_fast(fmaf(r2, r2, i2 * i2)) + beta));
        pu3 = fex2_fast(alpha * __log2f(fsqrt_fast(fmaf(r3, r3, i3 * i3)) + beta));
      }
      {   // final store (q = 7)
        float* sup = s_u + (QQ - 1) * QSTRIDE;
        if (LD == 0) {
          int f = ui0 >> 2; f ^= (f >> 3) & 7;
          reinterpret_cast<float4*>(sup)[f] = make_float4(pu0, pu1, pu2, pu3);
        } else {
          sup[swzw(ui0)]            = pu0;
          sup[swzw(ui0 + (1<<LD))]  = pu1;
          sup[swzw(ui0 + (2<<LD))]  = pu2;
          sup[swzw(ui0 + (3<<LD))]  = pu3;
        }
      }
    } else {
      // ---- boundary path: per-element t guards (stores unconditional) ----
#pragma unroll 1
      for (int q = 0; q < QQ; q++) {
        ull a0, a1, a2, a3;
        conv15(s_w2 + q * WSTRIDE, v, a0, a1, a2, a3);
        const float alpha = s_alpha[q];
        float* su = s_u + q * QSTRIDE;
#pragma unroll
        for (int r = 0; r < 4; r++) {
          const ull av = (r == 0) ? a0 : (r == 1) ? a1 : (r == 2) ? a2 : a3;
          const int ui = ui0 + (r << LD);
          float rr, ii2; unpack2(av, rr, ii2);
          const int t = tmin + ui;
          float u = 0.f;
          if (t >= 0 && t < NN) {
            const float hyp = fsqrt_fast(fmaf(rr, rr, ii2 * ii2));
            u = fex2_fast(alpha * __log2f(hyp + beta));
          }
          su[swzw(ui)] = u;
        }
      }
    }
  }
  __syncthreads();

  // ---- down stage: 512 (q, group-of-4-outputs) items over 2 reps ----
#pragma unroll
  for (int rep = 0; rep < 2; rep++) {
    const int w = tid + 256 * rep;
    const int q = w >> 6, g = w & 63;
    const float4* su4 = reinterpret_cast<const float4*>(s_u + q * QSTRIDE);
    float a[52];
#pragma unroll
    for (int mm = 0; mm < 13; mm++) {
      int f = 4 * g + mm; f ^= (f >> 3) & 7;
      const float4 qv = su4[f];
      a[4*mm] = qv.x; a[4*mm+1] = qv.y; a[4*mm+2] = qv.z; a[4*mm+3] = qv.w;
    }
    float acc0 = 0.f, acc1 = 0.f, acc2 = 0.f, acc3 = 0.f;
#pragma unroll
    for (int mm = 0; mm < 37; mm++) {
      const float gv = s_g[mm];
      acc0 = fmaf(gv, a[mm],      acc0);
      acc1 = fmaf(gv, a[mm + 4],  acc1);
      acc2 = fmaf(gv, a[mm + 8],  acc2);
      acc3 = fmaf(gv, a[mm + 12], acc3);
    }
    float4 o; o.x = acc0; o.y = acc1; o.z = acc2; o.w = acc3;
    float* dst = out + ((size_t)(b * OUTCH + j * CQ + c * QQ + q)) * OUTN
                     + o0 + 4 * g;
    *reinterpret_cast<float4*>(dst) = o;
  }
}

__global__ __launch_bounds__(256, 4) void scatter_all(
    const float* __restrict__ conv_w, const float* __restrict__ roots,
    const float* __restrict__ beta_p, float* __restrict__ out)
{
  __shared__ __align__(16) ull s_bp[BPF2];
  __shared__ float  s_u[QQ * QSTRIDE];
  __shared__ __align__(16) ull s_w2[QQ * WSTRIDE];
  __shared__ float  s_g[40];
  __shared__ float  s_alpha[QQ];

  const int j   = blockIdx.z;
  const int row = blockIdx.y;
  const int o0  = blockIdx.x * TOX;

  if (j <= 1)
    scatter_body<0>(s_bp, s_u, s_w2, s_g, s_alpha, j, row, o0, conv_w, roots, beta_p, out);
  else if (j == 2)
    scatter_body<1>(s_bp, s_u, s_w2, s_g, s_alpha, j, row, o0, conv_w, roots, beta_p, out);
  else if (j == 3)
    scatter_body<2>(s_bp, s_u, s_w2, s_g, s_alpha, j, row, o0, conv_w, roots, beta_p, out);
  else
    scatter_body<3>(s_bp, s_u, s_w2, s_g, s_alpha, j, row, o0, conv_w, roots, beta_p, out);
}

// ---------------- launch ----------------
extern "C" void kernel_launch(void* const* d_in, const int* in_sizes, int n_in,
                              void* d_out, int out_size)
{
  const float* x      = (const float*)d_in[0];
  const float* conv_w = (const float*)d_in[1];
  const float* roots  = (const float*)d_in[2];
  const float* beta   = (const float*)d_in[3];
  float* out = (float*)d_out;

  dim3 gW(NN / TILE_W, ROWS);                 // 32 x 16
  udtcwt_kernel<<<gW, 256>>>(x);

  dim3 gS(OUTN / TOX, ROWS, JLEV);            // 64 x 16 x 5 = 5120 CTAs
  scatter_all<<<gS, 256>>>(conv_w, roots, beta, out);
}

// round 15
// speedup vs baseline: 1.1133x; 1.1133x over previous
#include <cuda_runtime.h>
#include <cuda_bf16.h>
#include <math.h>

// ---------------- problem constants ----------------
#define NN      65536
#define ROWS    16      // BATCH*CH
#define JLEV    5
#define QQ      8
#define CQ      32      // QQ*CH
#define TT      15
#define OUTN    16384   // NN/4
#define OUTCH   160     // JLEV*CQ

typedef unsigned long long ull;

// ---------------- wavelet filters ----------------
__constant__ float c_H0O[13] = {
  -0.00455690456024f, -0.00543947593727f,  0.01702522388155f,  0.02382538479492f,
  -0.10671180468666f,  0.01186609203379f,  0.56881042071212f,  0.75614564389252f,
   0.27529538466888f, -0.11720388769911f, -0.03887280126882f,  0.03466034684485f,
  -0.00388321199915f };
__constant__ float c_H1O[13] = {
  -0.00388321199915f, -0.03466034684485f, -0.03887280126882f,  0.11720388769911f,
   0.27529538466888f, -0.75614564389252f,  0.56881042071212f, -0.01186609203379f,
  -0.10671180468666f, -0.02382538479492f,  0.01702522388155f,  0.00543947593727f,
  -0.00455690456024f };
__constant__ float c_H0A[10] = {
   0.03516384f, 0.0f, -0.08832942f, 0.23389032f, 0.76027237f,
   0.58751830f, 0.0f, -0.11430184f, 0.0f, 0.0f };
__constant__ float c_H0B[10] = {
   0.0f, 0.0f, -0.11430184f, 0.0f, 0.58751830f,
   0.76027237f, 0.23389032f, -0.08832942f, 0.0f, 0.03516384f };
__constant__ float c_H1A[10] = {
   0.0f, 0.0f, -0.11430184f, 0.0f, 0.58751830f,
  -0.76027237f, 0.23389032f, 0.08832942f, 0.0f, -0.03516384f };
__constant__ float c_H1B[10] = {
  -0.03516384f, 0.0f, 0.08832942f, 0.23389032f, -0.76027237f,
   0.58751830f, 0.0f, -0.11430184f, 0.0f, 0.0f };

// ---------------- scratch: interleaved (r,i) bandpass ----------------
__device__ float2 g_bp[(size_t)JLEV * ROWS * NN];

// ---------------- packed helpers / fast math ----------------
__device__ __forceinline__ ull pack2(float x, float y) {
  ull r; asm("mov.b64 %0, {%1, %2};" : "=l"(r) : "f"(x), "f"(y)); return r;
}
__device__ __forceinline__ void unpack2(ull v, float& x, float& y) {
  asm("mov.b64 {%0, %1}, %2;" : "=f"(x), "=f"(y) : "l"(v));
}
__device__ __forceinline__ ull ffma2(ull a, ull b, ull c) {
  ull d; asm("fma.rn.f32x2 %0, %1, %2, %3;" : "=l"(d) : "l"(a), "l"(b), "l"(c));
  return d;
}
__device__ __forceinline__ float fsqrt_fast(float x) {
  float r; asm("sqrt.approx.f32 %0, %1;" : "=f"(r) : "f"(x)); return r;
}
__device__ __forceinline__ float fex2_fast(float x) {
  float r; asm("ex2.approx.f32 %0, %1;" : "=f"(r) : "f"(x)); return r;
}

// ---------------- kernel 1: undecimated dual-tree CWT ----------------
#define TILE_W 2048
#define HALO   80
#define EXT    (TILE_W + 2*HALO)   // 2208

template<int D, int M>
__device__ __forceinline__ void tree_level(
    const float* la, const float* lb,
    float* la_n, float* lb_n,
    float2* __restrict__ bp)
{
  const int PAD = (D * 9) / 2;
  for (int i = threadIdx.x; i < TILE_W; i += 256) {
    const int s = HALO + i;
    float ar = 0.f, ai = 0.f;
#pragma unroll
    for (int k = 0; k < 10; k++) {
      ar = fmaf(c_H1A[k], la[s + D*k - PAD], ar);
      ai = fmaf(c_H1B[k], lb[s + D*k - PAD], ai);
    }
    bp[i] = make_float2(ar, ai);
  }
  if (la_n != nullptr) {
    for (int i = threadIdx.x; i < TILE_W + 2*M; i += 256) {
      const int s = HALO - M + i;
      float a = 0.f, b = 0.f;
#pragma unroll
      for (int k = 0; k < 10; k++) {
        a = fmaf(c_H0A[k], la[s + D*k - PAD], a);
        b = fmaf(c_H0B[k], lb[s + D*k - PAD], b);
      }
      la_n[s] = a; lb_n[s] = b;
    }
  }
}

__global__ __launch_bounds__(256) void udtcwt_kernel(const float* __restrict__ x)
{
  __shared__ float sA[EXT], sB[EXT], sC[EXT], sD[EXT];
  const int row = blockIdx.y;
  const int t0  = blockIdx.x * TILE_W;
  const float* xr = x + (size_t)row * NN;

  for (int s = threadIdx.x; s < EXT; s += 256) {
    const int g = t0 - HALO + s;
    sA[s] = (g >= 0 && g < NN) ? xr[g] : 0.f;
  }
  __syncthreads();

  {
    float2* outp = g_bp + ((size_t)(0*ROWS + row)) * NN + t0;
    for (int i = threadIdx.x; i < TILE_W; i += 256) {
      const int s = HALO + i;
      float acc = 0.f;
#pragma unroll
      for (int k = 0; k < 13; k++) acc = fmaf(c_H1O[k], sA[s + k - 6], acc);
      outp[i] = make_float2(acc, acc);
    }
    for (int i = threadIdx.x; i < TILE_W + 2*68; i += 256) {
      const int s = HALO - 68 + i;
      float acc = 0.f;
#pragma unroll
      for (int k = 0; k < 13; k++) acc = fmaf(c_H0O[k], sA[s + k - 6], acc);
      sB[s] = acc;
    }
  }
  __syncthreads();

  tree_level<1, 63>(sB, sB, sC, sD, g_bp + ((size_t)(1*ROWS + row))*NN + t0);
  __syncthreads();
  tree_level<2, 54>(sC, sD, sA, sB, g_bp + ((size_t)(2*ROWS + row))*NN + t0);
  __syncthreads();
  tree_level<4, 36>(sA, sB, sC, sD, g_bp + ((size_t)(3*ROWS + row))*NN + t0);
  __syncthreads();
  tree_level<8, 0>(sC, sD, (float*)nullptr, (float*)nullptr,
                   g_bp + ((size_t)(4*ROWS + row))*NN + t0);
}

// ---------------- kernel 2: all scales, q-amortized windows ----------------
#define TOX     256
#define ULEN    (4*TOX + 33)     // 1057
#define QSTRIDE 1088             // words per q in s_u (absorbs padded chunks)
#define BPF2    1300             // worst-case D*SPP (D=8: 8*161=1288)
#define WSTRIDE 16               // padded weights per q (16B-aligned pairs)

// word-granular swizzle matching float4-granular f^((f>>3)&7)
__device__ __forceinline__ int swzw(int i) { return i ^ (((i >> 5) & 7) << 2); }

// 15-tap packed conv on an 18-element window, weights as LDS.128 pairs
__device__ __forceinline__ void conv15(
    const ull* wq, const ull* v, ull& a0, ull& a1, ull& a2, ull& a3)
{
  const ulonglong2* wq2 = reinterpret_cast<const ulonglong2*>(wq);
  a0 = 0ull; a1 = 0ull; a2 = 0ull; a3 = 0ull;
#pragma unroll
  for (int h = 0; h < 7; h++) {           // taps 0..13 as pairs
    const ulonglong2 wp = wq2[h];
    const int k = 2 * h;
    a0 = ffma2(wp.x, v[k],     a0);
    a1 = ffma2(wp.x, v[k + 1], a1);
    a2 = ffma2(wp.x, v[k + 2], a2);
    a3 = ffma2(wp.x, v[k + 3], a3);
    a0 = ffma2(wp.y, v[k + 1], a0);
    a1 = ffma2(wp.y, v[k + 2], a1);
    a2 = ffma2(wp.y, v[k + 3], a2);
    a3 = ffma2(wp.y, v[k + 4], a3);
  }
  {                                        // tap 14 (scalar 64-bit load)
    const ull w14 = wq[14];
    a0 = ffma2(w14, v[14], a0);
    a1 = ffma2(w14, v[15], a1);
    a2 = ffma2(w14, v[16], a2);
    a3 = ffma2(w14, v[17], a3);
  }
}

template<int LD>
__device__ __forceinline__ void scatter_body(
    ull* s_bp, float* s_u, ull* s_w2, ull* s_g2, float* s_alpha,
    int j, int row, int o0,
    const float* __restrict__ conv_w, const float* __restrict__ roots,
    const float* __restrict__ beta_p, float* __restrict__ out)
{
  constexpr int D    = 1 << LD;
  constexpr int SU   = (ULEN + D - 1) / D;
  constexpr int CP   = (SU + 3) / 4;
  constexpr int CHK  = D * CP;
  constexpr int SLEN = 4 * CP + 18;
  constexpr int SPP  = ((SLEN + 15) & ~15) | 1;   // odd stride

  const int b = row >> 2, c = row & 3;
  const float inv_scale = exp2f(-0.5f * (float)j);
  const float beta = beta_p[0];
  const int tid  = threadIdx.x;
  const int tmin = 4 * o0 - 18;
  const int pmin = tmin - 7 * D;

  // global bp rows viewed as 64-bit words (float2 == 8B)
  const ull* bp8 = reinterpret_cast<const ull*>(
      g_bp + ((size_t)(j * ROWS + row)) * NN);

  // ---- fill phase-separated bp tile (direct 64-bit copies) ----
  for (int i = tid; i < D * SPP; i += 256) {
    const int p = i & (D - 1), s = i >> LD;
    const int idx = p * SPP + s;
    const int ii = (LD == 0) ? (idx ^ ((idx >> 4) & 3)) : idx;
    const int gi = pmin + i;
    s_bp[ii] = (gi >= 0 && gi < NN) ? bp8[gi] : 0ull;
  }
  if (tid < 19) {                    // packed composite /4 downsample filter
    float gpair[2];
#pragma unroll
    for (int e = 0; e < 2; e++) {
      const int m = 2 * tid + e;
      float acc = 0.f;
      for (int k = 0; k < 13; k++) {
        const int kp = m - 2 * k;
        if (kp >= 0 && kp < 13) acc += c_H0O[k] * c_H0O[kp];
      }
      gpair[e] = (m < 37) ? acc : 0.f;
    }
    s_g2[tid] = pack2(gpair[0], gpair[1]);
  }
  // weights pre-scaled by 2^(-j/2): folds the modulus normalization into the conv
  for (int i = tid; i < QQ * WSTRIDE; i += 256) {
    const int q = i >> 4, k = i & 15;
    const float wv = (k < TT)
        ? conv_w[(size_t)(j * CQ + c * QQ + q) * TT + k] * inv_scale : 0.f;
    s_w2[i] = pack2(wv, wv);
  }
  if (tid < QQ) {
    const float rt = roots[j * CQ + c * QQ + tid];
    s_alpha[tid] = 1.f / (1.f + __expf(-rt));
  }
  __syncthreads();

  // ---- u stage: one window load serves all 8 q; branch hoisted per chunk ----
  for (int m = tid; m < CHK; m += 256) {
    const int p = m & (D - 1), cc = m >> LD;
    const int base = p * SPP + 4 * cc;
    ull v[18];
#pragma unroll
    for (int t = 0; t < 18; t++) {
      const int idx = base + t;
      const int ii = (LD == 0) ? (idx ^ ((idx >> 4) & 3)) : idx;
      v[t] = s_bp[ii];                       // direct LDS.64 into pair
    }
    const int ui0 = p + ((4 * cc) << LD);
    const bool full = (tmin + ui0 >= 0) && (tmin + ui0 + (3 << LD) < NN);

    if (full) {
      // ---- hot path: no bounds checks, no per-q branching ----
#pragma unroll 1
      for (int q = 0; q < QQ; q++) {
        ull a0, a1, a2, a3;
        conv15(s_w2 + q * WSTRIDE, v, a0, a1, a2, a3);
        const float alpha = s_alpha[q];
        float* su = s_u + q * QSTRIDE;

        float r0, i0, r1, i1, r2, i2, r3, i3;
        unpack2(a0, r0, i0); unpack2(a1, r1, i1);
        unpack2(a2, r2, i2); unpack2(a3, r3, i3);
        const float h0 = fsqrt_fast(fmaf(r0, r0, i0 * i0));
        const float h1 = fsqrt_fast(fmaf(r1, r1, i1 * i1));
        const float h2 = fsqrt_fast(fmaf(r2, r2, i2 * i2));
        const float h3 = fsqrt_fast(fmaf(r3, r3, i3 * i3));
        const float u0 = fex2_fast(alpha * __log2f(h0 + beta));
        const float u1 = fex2_fast(alpha * __log2f(h1 + beta));
        const float u2 = fex2_fast(alpha * __log2f(h2 + beta));
        const float u3 = fex2_fast(alpha * __log2f(h3 + beta));
        if (LD == 0) {
          int f = ui0 >> 2; f ^= (f >> 3) & 7;
          reinterpret_cast<float4*>(su)[f] = make_float4(u0, u1, u2, u3);
        } else {
          su[swzw(ui0)]            = u0;
          su[swzw(ui0 + (1<<LD))]  = u1;
          su[swzw(ui0 + (2<<LD))]  = u2;
          su[swzw(ui0 + (3<<LD))]  = u3;
        }
      }
    } else {
      // ---- boundary path: per-element t guards (stores unconditional) ----
#pragma unroll 1
      for (int q = 0; q < QQ; q++) {
        ull a0, a1, a2, a3;
        conv15(s_w2 + q * WSTRIDE, v, a0, a1, a2, a3);
        const float alpha = s_alpha[q];
        float* su = s_u + q * QSTRIDE;
#pragma unroll
        for (int r = 0; r < 4; r++) {
          const ull av = (r == 0) ? a0 : (r == 1) ? a1 : (r == 2) ? a2 : a3;
          const int ui = ui0 + (r << LD);
          float rr, ii2; unpack2(av, rr, ii2);
          const int t = tmin + ui;
          float u = 0.f;
          if (t >= 0 && t < NN) {
            const float hyp = fsqrt_fast(fmaf(rr, rr, ii2 * ii2));
            u = fex2_fast(alpha * __log2f(hyp + beta));
          }
          su[swzw(ui)] = u;
        }
      }
    }
  }
  __syncthreads();

  // ---- down stage: packed FFMA2, 512 (q, group-of-4) items over 2 reps ----
#pragma unroll
  for (int rep = 0; rep < 2; rep++) {
    const int w = tid + 256 * rep;
    const int q = w >> 6, g = w & 63;
    const ulonglong2* su2 = reinterpret_cast<const ulonglong2*>(s_u + q * QSTRIDE);
    ull a2[26];
#pragma unroll
    for (int mm = 0; mm < 13; mm++) {
      int f = 4 * g + mm; f ^= (f >> 3) & 7;
      const ulonglong2 t = su2[f];
      a2[2*mm]   = t.x;
      a2[2*mm+1] = t.y;
    }
    float4 o;
    float* op = &o.x;
#pragma unroll
    for (int r = 0; r < 4; r++) {
      ull acc = 0ull;
#pragma unroll
      for (int s = 0; s < 19; s++)          // taps 0..37 (g[37]=0)
        acc = ffma2(s_g2[s], a2[2*r + s], acc);
      float lo, hi; unpack2(acc, lo, hi);
      op[r] = lo + hi;
    }
    float* dst = out + ((size_t)(b * OUTCH + j * CQ + c * QQ + q)) * OUTN
                     + o0 + 4 * g;
    *reinterpret_cast<float4*>(dst) = o;
  }
}

__global__ __launch_bounds__(256, 4) void scatter_all(
    const float* __restrict__ conv_w, const float* __restrict__ roots,
    const float* __restrict__ beta_p, float* __restrict__ out)
{
  __shared__ __align__(16) ull s_bp[BPF2];
  __shared__ float  s_u[QQ * QSTRIDE];
  __shared__ __align__(16) ull s_w2[QQ * WSTRIDE];
  __shared__ __align__(16) ull s_g2[20];
  __shared__ float  s_alpha[QQ];

  const int j   = blockIdx.z;
  const int row = blockIdx.y;
  const int o0  = blockIdx.x * TOX;

  if (j <= 1)
    scatter_body<0>(s_bp, s_u, s_w2, s_g2, s_alpha, j, row, o0, conv_w, roots, beta_p, out);
  else if (j == 2)
    scatter_body<1>(s_bp, s_u, s_w2, s_g2, s_alpha, j, row, o0, conv_w, roots, beta_p, out);
  else if (j == 3)
    scatter_body<2>(s_bp, s_u, s_w2, s_g2, s_alpha, j, row, o0, conv_w, roots, beta_p, out);
  else
    scatter_body<3>(s_bp, s_u, s_w2, s_g2, s_alpha, j, row, o0, conv_w, roots, beta_p, out);
}

// ---------------- launch ----------------
extern "C" void kernel_launch(void* const* d_in, const int* in_sizes, int n_in,
                              void* d_out, int out_size)
{
  const float* x      = (const float*)d_in[0];
  const float* conv_w = (const float*)d_in[1];
  const float* roots  = (const float*)d_in[2];
  const float* beta   = (const float*)d_in[3];
  float* out = (float*)d_out;

  dim3 gW(NN / TILE_W, ROWS);                 // 32 x 16
  udtcwt_kernel<<<gW, 256>>>(x);

  dim3 gS(OUTN / TOX, ROWS, JLEV);            // 64 x 16 x 5 = 5120 CTAs
  scatter_all<<<gS, 256>>>(conv_w, roots, beta, out);
}

// round 16
// speedup vs baseline: 1.2419x; 1.1155x over previous
#include <cuda_runtime.h>
#include <cuda_bf16.h>
#include <math.h>

// ---------------- problem constants ----------------
#define NN      65536
#define ROWS    16      // BATCH*CH
#define JLEV    5
#define QQ      8
#define CQ      32      // QQ*CH
#define TT      15
#define OUTN    16384   // NN/4
#define OUTCH   160     // JLEV*CQ

typedef unsigned long long ull;

// ---------------- wavelet filters ----------------
__constant__ float c_H0O[13] = {
  -0.00455690456024f, -0.00543947593727f,  0.01702522388155f,  0.02382538479492f,
  -0.10671180468666f,  0.01186609203379f,  0.56881042071212f,  0.75614564389252f,
   0.27529538466888f, -0.11720388769911f, -0.03887280126882f,  0.03466034684485f,
  -0.00388321199915f };
__constant__ float c_H1O[13] = {
  -0.00388321199915f, -0.03466034684485f, -0.03887280126882f,  0.11720388769911f,
   0.27529538466888f, -0.75614564389252f,  0.56881042071212f, -0.01186609203379f,
  -0.10671180468666f, -0.02382538479492f,  0.01702522388155f,  0.00543947593727f,
  -0.00455690456024f };
__constant__ float c_H0A[10] = {
   0.03516384f, 0.0f, -0.08832942f, 0.23389032f, 0.76027237f,
   0.58751830f, 0.0f, -0.11430184f, 0.0f, 0.0f };
__constant__ float c_H0B[10] = {
   0.0f, 0.0f, -0.11430184f, 0.0f, 0.58751830f,
   0.76027237f, 0.23389032f, -0.08832942f, 0.0f, 0.03516384f };
__constant__ float c_H1A[10] = {
   0.0f, 0.0f, -0.11430184f, 0.0f, 0.58751830f,
  -0.76027237f, 0.23389032f, 0.08832942f, 0.0f, -0.03516384f };
__constant__ float c_H1B[10] = {
  -0.03516384f, 0.0f, 0.08832942f, 0.23389032f, -0.76027237f,
   0.58751830f, 0.0f, -0.11430184f, 0.0f, 0.0f };

// ---------------- scratch: interleaved (r,i) bandpass ----------------
__device__ float2 g_bp[(size_t)JLEV * ROWS * NN];

// ---------------- packed helpers / fast math ----------------
__device__ __forceinline__ ull pack2(float x, float y) {
  ull r; asm("mov.b64 %0, {%1, %2};" : "=l"(r) : "f"(x), "f"(y)); return r;
}
__device__ __forceinline__ void unpack2(ull v, float& x, float& y) {
  asm("mov.b64 {%0, %1}, %2;" : "=f"(x), "=f"(y) : "l"(v));
}
__device__ __forceinline__ ull ffma2(ull a, ull b, ull c) {
  ull d; asm("fma.rn.f32x2 %0, %1, %2, %3;" : "=l"(d) : "l"(a), "l"(b), "l"(c));
  return d;
}
__device__ __forceinline__ float fsqrt_fast(float x) {
  float r; asm("sqrt.approx.f32 %0, %1;" : "=f"(r) : "f"(x)); return r;
}
__device__ __forceinline__ float fex2_fast(float x) {
  float r; asm("ex2.approx.f32 %0, %1;" : "=f"(r) : "f"(x)); return r;
}

// ---------------- kernel 1: undecimated dual-tree CWT ----------------
#define TILE_W 2048
#define HALO   80
#define EXT    (TILE_W + 2*HALO)   // 2208

template<int D, int M>
__device__ __forceinline__ void tree_level(
    const float* la, const float* lb,
    float* la_n, float* lb_n,
    float2* __restrict__ bp)
{
  const int PAD = (D * 9) / 2;
  for (int i = threadIdx.x; i < TILE_W; i += 256) {
    const int s = HALO + i;
    float ar = 0.f, ai = 0.f;
#pragma unroll
    for (int k = 0; k < 10; k++) {
      ar = fmaf(c_H1A[k], la[s + D*k - PAD], ar);
      ai = fmaf(c_H1B[k], lb[s + D*k - PAD], ai);
    }
    bp[i] = make_float2(ar, ai);
  }
  if (la_n != nullptr) {
    for (int i = threadIdx.x; i < TILE_W + 2*M; i += 256) {
      const int s = HALO - M + i;
      float a = 0.f, b = 0.f;
#pragma unroll
      for (int k = 0; k < 10; k++) {
        a = fmaf(c_H0A[k], la[s + D*k - PAD], a);
        b = fmaf(c_H0B[k], lb[s + D*k - PAD], b);
      }
      la_n[s] = a; lb_n[s] = b;
    }
  }
}

__global__ __launch_bounds__(256) void udtcwt_kernel(const float* __restrict__ x)
{
  __shared__ float sA[EXT], sB[EXT], sC[EXT], sD[EXT];
  const int row = blockIdx.y;
  const int t0  = blockIdx.x * TILE_W;
  const float* xr = x + (size_t)row * NN;

  for (int s = threadIdx.x; s < EXT; s += 256) {
    const int g = t0 - HALO + s;
    sA[s] = (g >= 0 && g < NN) ? xr[g] : 0.f;
  }
  __syncthreads();

  {
    float2* outp = g_bp + ((size_t)(0*ROWS + row)) * NN + t0;
    for (int i = threadIdx.x; i < TILE_W; i += 256) {
      const int s = HALO + i;
      float acc = 0.f;
#pragma unroll
      for (int k = 0; k < 13; k++) acc = fmaf(c_H1O[k], sA[s + k - 6], acc);
      outp[i] = make_float2(acc, acc);
    }
    for (int i = threadIdx.x; i < TILE_W + 2*68; i += 256) {
      const int s = HALO - 68 + i;
      float acc = 0.f;
#pragma unroll
      for (int k = 0; k < 13; k++) acc = fmaf(c_H0O[k], sA[s + k - 6], acc);
      sB[s] = acc;
    }
  }
  __syncthreads();

  tree_level<1, 63>(sB, sB, sC, sD, g_bp + ((size_t)(1*ROWS + row))*NN + t0);
  __syncthreads();
  tree_level<2, 54>(sC, sD, sA, sB, g_bp + ((size_t)(2*ROWS + row))*NN + t0);
  __syncthreads();
  tree_level<4, 36>(sA, sB, sC, sD, g_bp + ((size_t)(3*ROWS + row))*NN + t0);
  __syncthreads();
  tree_level<8, 0>(sC, sD, (float*)nullptr, (float*)nullptr,
                   g_bp + ((size_t)(4*ROWS + row))*NN + t0);
}

// ---------------- kernel 2: all scales, q-amortized windows ----------------
#define TOX     256
#define ULEN    (4*TOX + 33)     // 1057
#define QSTRIDE 1088             // words per q in s_u (absorbs padded chunks)
#define BPF2    1300             // worst-case D*SPP (D=8: 8*161=1288)
#define WSTRIDE 16               // padded weights per q (16B-aligned pairs)

// word-granular swizzle matching float4-granular f^((f>>3)&7)
__device__ __forceinline__ int swzw(int i) { return i ^ (((i >> 5) & 7) << 2); }

// 15-tap packed conv on an 18-element window, weights as LDS.128 pairs
__device__ __forceinline__ void conv15(
    const ull* wq, const ull* v, ull& a0, ull& a1, ull& a2, ull& a3)
{
  const ulonglong2* wq2 = reinterpret_cast<const ulonglong2*>(wq);
  a0 = 0ull; a1 = 0ull; a2 = 0ull; a3 = 0ull;
#pragma unroll
  for (int h = 0; h < 7; h++) {           // taps 0..13 as pairs
    const ulonglong2 wp = wq2[h];
    const int k = 2 * h;
    a0 = ffma2(wp.x, v[k],     a0);
    a1 = ffma2(wp.x, v[k + 1], a1);
    a2 = ffma2(wp.x, v[k + 2], a2);
    a3 = ffma2(wp.x, v[k + 3], a3);
    a0 = ffma2(wp.y, v[k + 1], a0);
    a1 = ffma2(wp.y, v[k + 2], a1);
    a2 = ffma2(wp.y, v[k + 3], a2);
    a3 = ffma2(wp.y, v[k + 4], a3);
  }
  {                                        // tap 14 (scalar 64-bit load)
    const ull w14 = wq[14];
    a0 = ffma2(w14, v[14], a0);
    a1 = ffma2(w14, v[15], a1);
    a2 = ffma2(w14, v[16], a2);
    a3 = ffma2(w14, v[17], a3);
  }
}

template<int LD>
__device__ __forceinline__ void scatter_body(
    ull* s_bp, float* s_u, ull* s_w2, ull* s_g2, float* s_alpha,
    int j, int row, int o0,
    const float* __restrict__ conv_w, const float* __restrict__ roots,
    const float* __restrict__ beta_p, float* __restrict__ out)
{
  constexpr int D    = 1 << LD;
  constexpr int SU   = (ULEN + D - 1) / D;
  constexpr int CP   = (SU + 3) / 4;
  constexpr int CHK  = D * CP;
  constexpr int SLEN = 4 * CP + 18;
  constexpr int SPP  = ((SLEN + 15) & ~15) | 1;   // odd stride

  const int b = row >> 2, c = row & 3;
  const float inv_scale = exp2f(-0.5f * (float)j);
  const float beta = beta_p[0];
  const int tid  = threadIdx.x;
  const int tmin = 4 * o0 - 18;
  const int pmin = tmin - 7 * D;

  // global bp rows viewed as 64-bit words (float2 == 8B)
  const ull* bp8 = reinterpret_cast<const ull*>(
      g_bp + ((size_t)(j * ROWS + row)) * NN);

  // ---- fill phase-separated bp tile (direct 64-bit copies) ----
  for (int i = tid; i < D * SPP; i += 256) {
    const int p = i & (D - 1), s = i >> LD;
    const int idx = p * SPP + s;
    const int ii = (LD == 0) ? (idx ^ ((idx >> 4) & 3)) : idx;
    const int gi = pmin + i;
    s_bp[ii] = (gi >= 0 && gi < NN) ? bp8[gi] : 0ull;
  }
  if (tid < 19) {                    // packed composite /4 downsample filter
    float gpair[2];
#pragma unroll
    for (int e = 0; e < 2; e++) {
      const int m = 2 * tid + e;
      float acc = 0.f;
      for (int k = 0; k < 13; k++) {
        const int kp = m - 2 * k;
        if (kp >= 0 && kp < 13) acc += c_H0O[k] * c_H0O[kp];
      }
      gpair[e] = (m < 37) ? acc : 0.f;
    }
    s_g2[tid] = pack2(gpair[0], gpair[1]);
  }
  // weights pre-scaled by 2^(-j/2): folds the modulus normalization into the conv
  for (int i = tid; i < QQ * WSTRIDE; i += 256) {
    const int q = i >> 4, k = i & 15;
    const float wv = (k < TT)
        ? conv_w[(size_t)(j * CQ + c * QQ + q) * TT + k] * inv_scale : 0.f;
    s_w2[i] = pack2(wv, wv);
  }
  if (tid < QQ) {
    const float rt = roots[j * CQ + c * QQ + tid];
    s_alpha[tid] = 1.f / (1.f + __expf(-rt));
  }
  __syncthreads();

  // ---- u stage: one window load serves all 8 q; branch hoisted per chunk ----
  for (int m = tid; m < CHK; m += 256) {
    const int p = m & (D - 1), cc = m >> LD;
    const int base = p * SPP + 4 * cc;
    ull v[18];
#pragma unroll
    for (int t = 0; t < 18; t++) {
      const int idx = base + t;
      const int ii = (LD == 0) ? (idx ^ ((idx >> 4) & 3)) : idx;
      v[t] = s_bp[ii];                       // direct LDS.64 into pair
    }
    const int ui0 = p + ((4 * cc) << LD);
    const bool full = (tmin + ui0 >= 0) && (tmin + ui0 + (3 << LD) < NN);

    if (full) {
      // ---- hot path: no bounds checks, no per-q branching ----
#pragma unroll 1
      for (int q = 0; q < QQ; q++) {
        ull a0, a1, a2, a3;
        conv15(s_w2 + q * WSTRIDE, v, a0, a1, a2, a3);
        const float alpha = s_alpha[q];
        float* su = s_u + q * QSTRIDE;

        float r0, i0, r1, i1, r2, i2, r3, i3;
        unpack2(a0, r0, i0); unpack2(a1, r1, i1);
        unpack2(a2, r2, i2); unpack2(a3, r3, i3);
        const float h0 = fsqrt_fast(fmaf(r0, r0, i0 * i0));
        const float h1 = fsqrt_fast(fmaf(r1, r1, i1 * i1));
        const float h2 = fsqrt_fast(fmaf(r2, r2, i2 * i2));
        const float h3 = fsqrt_fast(fmaf(r3, r3, i3 * i3));
        const float u0 = fex2_fast(alpha * __log2f(h0 + beta));
        const float u1 = fex2_fast(alpha * __log2f(h1 + beta));
        const float u2 = fex2_fast(alpha * __log2f(h2 + beta));
        const float u3 = fex2_fast(alpha * __log2f(h3 + beta));
        if (LD == 0) {
          int f = ui0 >> 2; f ^= (f >> 3) & 7;
          reinterpret_cast<float4*>(su)[f] = make_float4(u0, u1, u2, u3);
        } else {
          su[swzw(ui0)]            = u0;
          su[swzw(ui0 + (1<<LD))]  = u1;
          su[swzw(ui0 + (2<<LD))]  = u2;
          su[swzw(ui0 + (3<<LD))]  = u3;
        }
      }
    } else {
      // ---- boundary path: per-element t guards (stores unconditional) ----
#pragma unroll 1
      for (int q = 0; q < QQ; q++) {
        ull a0, a1, a2, a3;
        conv15(s_w2 + q * WSTRIDE, v, a0, a1, a2, a3);
        const float alpha = s_alpha[q];
        float* su = s_u + q * QSTRIDE;
#pragma unroll
        for (int r = 0; r < 4; r++) {
          const ull av = (r == 0) ? a0 : (r == 1) ? a1 : (r == 2) ? a2 : a3;
          const int ui = ui0 + (r << LD);
          float rr, ii2; unpack2(av, rr, ii2);
          const int t = tmin + ui;
          float u = 0.f;
          if (t >= 0 && t < NN) {
            const float hyp = fsqrt_fast(fmaf(rr, rr, ii2 * ii2));
            u = fex2_fast(alpha * __log2f(hyp + beta));
          }
          su[swzw(ui)] = u;
        }
      }
    }
  }
  __syncthreads();

  // ---- down stage: packed FFMA2, consume-on-load (no window array) ----
#pragma unroll
  for (int rep = 0; rep < 2; rep++) {
    const int w = tid + 256 * rep;
    const int q = w >> 6, g = w & 63;
    const ulonglong2* su2 = reinterpret_cast<const ulonglong2*>(s_u + q * QSTRIDE);
    ull acc[4] = {0ull, 0ull, 0ull, 0ull};
#pragma unroll
    for (int mm = 0; mm < 13; mm++) {
      int f = 4 * g + mm; f ^= (f >> 3) & 7;
      const ulonglong2 t = su2[f];
      // words 2mm (t.x) and 2mm+1 (t.y): acc[r] += g2[w - 2r] * word[w]
#pragma unroll
      for (int r = 0; r < 4; r++) {
        const int s0 = 2 * mm - 2 * r;
        if (s0 >= 0 && s0 < 19) acc[r] = ffma2(s_g2[s0], t.x, acc[r]);
        const int s1 = s0 + 1;
        if (s1 >= 0 && s1 < 19) acc[r] = ffma2(s_g2[s1], t.y, acc[r]);
      }
    }
    float4 o;
    float* op = &o.x;
#pragma unroll
    for (int r = 0; r < 4; r++) {
      float lo, hi; unpack2(acc[r], lo, hi);
      op[r] = lo + hi;
    }
    float* dst = out + ((size_t)(b * OUTCH + j * CQ + c * QQ + q)) * OUTN
                     + o0 + 4 * g;
    *reinterpret_cast<float4*>(dst) = o;
  }
}

__global__ __launch_bounds__(256, 4) void scatter_all(
    const float* __restrict__ conv_w, const float* __restrict__ roots,
    const float* __restrict__ beta_p, float* __restrict__ out)
{
  __shared__ __align__(16) ull s_bp[BPF2];
  __shared__ float  s_u[QQ * QSTRIDE];
  __shared__ __align__(16) ull s_w2[QQ * WSTRIDE];
  __shared__ __align__(16) ull s_g2[20];
  __shared__ float  s_alpha[QQ];

  const int j   = blockIdx.z;
  const int row = blockIdx.y;
  const int o0  = blockIdx.x * TOX;

  if (j <= 1)
    scatter_body<0>(s_bp, s_u, s_w2, s_g2, s_alpha, j, row, o0, conv_w, roots, beta_p, out);
  else if (j == 2)
    scatter_body<1>(s_bp, s_u, s_w2, s_g2, s_alpha, j, row, o0, conv_w, roots, beta_p, out);
  else if (j == 3)
    scatter_body<2>(s_bp, s_u, s_w2, s_g2, s_alpha, j, row, o0, conv_w, roots, beta_p, out);
  else
    scatter_body<3>(s_bp, s_u, s_w2, s_g2, s_alpha, j, row, o0, conv_w, roots, beta_p, out);
}

// ---------------- launch ----------------
extern "C" void kernel_launch(void* const* d_in, const int* in_sizes, int n_in,
                              void* d_out, int out_size)
{
  const float* x      = (const float*)d_in[0];
  const float* conv_w = (const float*)d_in[1];
  const float* roots  = (const float*)d_in[2];
  const float* beta   = (const float*)d_in[3];
  float* out = (float*)d_out;

  dim3 gW(NN / TILE_W, ROWS);                 // 32 x 16
  udtcwt_kernel<<<gW, 256>>>(x);

  dim3 gS(OUTN / TOX, ROWS, JLEV);            // 64 x 16 x 5 = 5120 CTAs
  scatter_all<<<gS, 256>>>(conv_w, roots, beta, out);
}

// round 17
// speedup vs baseline: 1.2638x; 1.0177x over previous
#include <cuda_runtime.h>
#include <cuda_bf16.h>
#include <math.h>

// ---------------- problem constants ----------------
#define NN      65536
#define ROWS    16      // BATCH*CH
#define JLEV    5
#define QQ      8
#define CQ      32      // QQ*CH
#define TT      15
#define OUTN    16384   // NN/4
#define OUTCH   160     // JLEV*CQ

typedef unsigned long long ull;

// ---------------- wavelet filters ----------------
__constant__ float c_H0O[13] = {
  -0.00455690456024f, -0.00543947593727f,  0.01702522388155f,  0.02382538479492f,
  -0.10671180468666f,  0.01186609203379f,  0.56881042071212f,  0.75614564389252f,
   0.27529538466888f, -0.11720388769911f, -0.03887280126882f,  0.03466034684485f,
  -0.00388321199915f };
__constant__ float c_H1O[13] = {
  -0.00388321199915f, -0.03466034684485f, -0.03887280126882f,  0.11720388769911f,
   0.27529538466888f, -0.75614564389252f,  0.56881042071212f, -0.01186609203379f,
  -0.10671180468666f, -0.02382538479492f,  0.01702522388155f,  0.00543947593727f,
  -0.00455690456024f };
__constant__ float c_H0A[10] = {
   0.03516384f, 0.0f, -0.08832942f, 0.23389032f, 0.76027237f,
   0.58751830f, 0.0f, -0.11430184f, 0.0f, 0.0f };
__constant__ float c_H0B[10] = {
   0.0f, 0.0f, -0.11430184f, 0.0f, 0.58751830f,
   0.76027237f, 0.23389032f, -0.08832942f, 0.0f, 0.03516384f };
__constant__ float c_H1A[10] = {
   0.0f, 0.0f, -0.11430184f, 0.0f, 0.58751830f,
  -0.76027237f, 0.23389032f, 0.08832942f, 0.0f, -0.03516384f };
__constant__ float c_H1B[10] = {
  -0.03516384f, 0.0f, 0.08832942f, 0.23389032f, -0.76027237f,
   0.58751830f, 0.0f, -0.11430184f, 0.0f, 0.0f };

// ---------------- scratch: interleaved (r,i) bandpass ----------------
__device__ float2 g_bp[(size_t)JLEV * ROWS * NN];

// ---------------- packed helpers / fast math ----------------
__device__ __forceinline__ ull pack2(float x, float y) {
  ull r; asm("mov.b64 %0, {%1, %2};" : "=l"(r) : "f"(x), "f"(y)); return r;
}
__device__ __forceinline__ void unpack2(ull v, float& x, float& y) {
  asm("mov.b64 {%0, %1}, %2;" : "=f"(x), "=f"(y) : "l"(v));
}
__device__ __forceinline__ ull ffma2(ull a, ull b, ull c) {
  ull d; asm("fma.rn.f32x2 %0, %1, %2, %3;" : "=l"(d) : "l"(a), "l"(b), "l"(c));
  return d;
}
__device__ __forceinline__ float fsqrt_fast(float x) {
  float r; asm("sqrt.approx.f32 %0, %1;" : "=f"(r) : "f"(x)); return r;
}
__device__ __forceinline__ float fex2_fast(float x) {
  float r; asm("ex2.approx.f32 %0, %1;" : "=f"(r) : "f"(x)); return r;
}

// ---------------- kernel 1: undecimated dual-tree CWT ----------------
#define TILE_W 1024
#define HALO   80
#define EXT    (TILE_W + 2*HALO)   // 1184

template<int D, int M>
__device__ __forceinline__ void tree_level(
    const float* la, const float* lb,
    float* la_n, float* lb_n,
    float2* __restrict__ bp)
{
  const int PAD = (D * 9) / 2;
  for (int i = threadIdx.x; i < TILE_W; i += 256) {
    const int s = HALO + i;
    float ar = 0.f, ai = 0.f;
#pragma unroll
    for (int k = 0; k < 10; k++) {
      ar = fmaf(c_H1A[k], la[s + D*k - PAD], ar);
      ai = fmaf(c_H1B[k], lb[s + D*k - PAD], ai);
    }
    bp[i] = make_float2(ar, ai);
  }
  if (la_n != nullptr) {
    for (int i = threadIdx.x; i < TILE_W + 2*M; i += 256) {
      const int s = HALO - M + i;
      float a = 0.f, b = 0.f;
#pragma unroll
      for (int k = 0; k < 10; k++) {
        a = fmaf(c_H0A[k], la[s + D*k - PAD], a);
        b = fmaf(c_H0B[k], lb[s + D*k - PAD], b);
      }
      la_n[s] = a; lb_n[s] = b;
    }
  }
}

__global__ __launch_bounds__(256) void udtcwt_kernel(const float* __restrict__ x)
{
  __shared__ float sA[EXT], sB[EXT], sC[EXT], sD[EXT];
  const int row = blockIdx.y;
  const int t0  = blockIdx.x * TILE_W;
  const float* xr = x + (size_t)row * NN;

  for (int s = threadIdx.x; s < EXT; s += 256) {
    const int g = t0 - HALO + s;
    sA[s] = (g >= 0 && g < NN) ? xr[g] : 0.f;
  }
  __syncthreads();

  {
    float2* outp = g_bp + ((size_t)(0*ROWS + row)) * NN + t0;
    for (int i = threadIdx.x; i < TILE_W; i += 256) {
      const int s = HALO + i;
      float acc = 0.f;
#pragma unroll
      for (int k = 0; k < 13; k++) acc = fmaf(c_H1O[k], sA[s + k - 6], acc);
      outp[i] = make_float2(acc, acc);
    }
    for (int i = threadIdx.x; i < TILE_W + 2*68; i += 256) {
      const int s = HALO - 68 + i;
      float acc = 0.f;
#pragma unroll
      for (int k = 0; k < 13; k++) acc = fmaf(c_H0O[k], sA[s + k - 6], acc);
      sB[s] = acc;
    }
  }
  __syncthreads();

  tree_level<1, 63>(sB, sB, sC, sD, g_bp + ((size_t)(1*ROWS + row))*NN + t0);
  __syncthreads();
  tree_level<2, 54>(sC, sD, sA, sB, g_bp + ((size_t)(2*ROWS + row))*NN + t0);
  __syncthreads();
  tree_level<4, 36>(sA, sB, sC, sD, g_bp + ((size_t)(3*ROWS + row))*NN + t0);
  __syncthreads();
  tree_level<8, 0>(sC, sD, (float*)nullptr, (float*)nullptr,
                   g_bp + ((size_t)(4*ROWS + row))*NN + t0);
}

// ---------------- kernel 2: all scales, q-amortized windows ----------------
#define TOX     256
#define ULEN    (4*TOX + 33)     // 1057
#define QSTRIDE 1088             // words per q in s_u (absorbs padded chunks)
#define BPF2    1300             // worst-case D*SPP (D=8: 8*161=1288)
#define WSTRIDE 16               // padded weights per q (16B-aligned pairs)

// word-granular swizzle matching float4-granular f^((f>>3)&7)
__device__ __forceinline__ int swzw(int i) { return i ^ (((i >> 5) & 7) << 2); }

// 15-tap packed conv on an 18-element window, weights as LDS.128 pairs
__device__ __forceinline__ void conv15(
    const ull* wq, const ull* v, ull& a0, ull& a1, ull& a2, ull& a3)
{
  const ulonglong2* wq2 = reinterpret_cast<const ulonglong2*>(wq);
  a0 = 0ull; a1 = 0ull; a2 = 0ull; a3 = 0ull;
#pragma unroll
  for (int h = 0; h < 7; h++) {           // taps 0..13 as pairs
    const ulonglong2 wp = wq2[h];
    const int k = 2 * h;
    a0 = ffma2(wp.x, v[k],     a0);
    a1 = ffma2(wp.x, v[k + 1], a1);
    a2 = ffma2(wp.x, v[k + 2], a2);
    a3 = ffma2(wp.x, v[k + 3], a3);
    a0 = ffma2(wp.y, v[k + 1], a0);
    a1 = ffma2(wp.y, v[k + 2], a1);
    a2 = ffma2(wp.y, v[k + 3], a2);
    a3 = ffma2(wp.y, v[k + 4], a3);
  }
  {                                        // tap 14 (scalar 64-bit load)
    const ull w14 = wq[14];
    a0 = ffma2(w14, v[14], a0);
    a1 = ffma2(w14, v[15], a1);
    a2 = ffma2(w14, v[16], a2);
    a3 = ffma2(w14, v[17], a3);
  }
}

template<int LD>
__device__ __forceinline__ void scatter_body(
    ull* s_bp, float* s_u, ull* s_w2, ull* s_g2, float* s_alpha,
    int j, int row, int o0,
    const float* __restrict__ conv_w, const float* __restrict__ roots,
    const float* __restrict__ beta_p, float* __restrict__ out)
{
  constexpr int D    = 1 << LD;
  constexpr int SU   = (ULEN + D - 1) / D;
  constexpr int CP   = (SU + 3) / 4;
  constexpr int CHK  = D * CP;
  constexpr int SLEN = 4 * CP + 18;
  constexpr int SPP  = ((SLEN + 15) & ~15) | 1;   // odd stride

  const int b = row >> 2, c = row & 3;
  const float inv_scale = exp2f(-0.5f * (float)j);
  const float beta = beta_p[0];
  const int tid  = threadIdx.x;
  const int tmin = 4 * o0 - 18;
  const int pmin = tmin - 7 * D;

  // global bp rows viewed as 64-bit words (float2 == 8B)
  const ull* bp8 = reinterpret_cast<const ull*>(
      g_bp + ((size_t)(j * ROWS + row)) * NN);

  // ---- fill phase-separated bp tile (direct 64-bit copies) ----
  for (int i = tid; i < D * SPP; i += 256) {
    const int p = i & (D - 1), s = i >> LD;
    const int idx = p * SPP + s;
    const int ii = (LD == 0) ? (idx ^ ((idx >> 4) & 3)) : idx;
    const int gi = pmin + i;
    s_bp[ii] = (gi >= 0 && gi < NN) ? bp8[gi] : 0ull;
  }
  if (tid < 20) {                    // packed composite /4 downsample filter
    float gpair[2];
#pragma unroll
    for (int e = 0; e < 2; e++) {
      const int m = 2 * tid + e;
      float acc = 0.f;
      for (int k = 0; k < 13; k++) {
        const int kp = m - 2 * k;
        if (kp >= 0 && kp < 13) acc += c_H0O[k] * c_H0O[kp];
      }
      gpair[e] = (m < 37) ? acc : 0.f;
    }
    s_g2[tid] = pack2(gpair[0], gpair[1]);
  }
  // weights pre-scaled by 2^(-j/2): folds the modulus normalization into the conv
  for (int i = tid; i < QQ * WSTRIDE; i += 256) {
    const int q = i >> 4, k = i & 15;
    const float wv = (k < TT)
        ? conv_w[(size_t)(j * CQ + c * QQ + q) * TT + k] * inv_scale : 0.f;
    s_w2[i] = pack2(wv, wv);
  }
  if (tid < QQ) {
    const float rt = roots[j * CQ + c * QQ + tid];
    s_alpha[tid] = 1.f / (1.f + __expf(-rt));
  }
  __syncthreads();

  // ---- u stage: one window load serves all 8 q; branch hoisted per chunk ----
  for (int m = tid; m < CHK; m += 256) {
    const int p = m & (D - 1), cc = m >> LD;
    const int base = p * SPP + 4 * cc;
    ull v[18];
#pragma unroll
    for (int t = 0; t < 18; t++) {
      const int idx = base + t;
      const int ii = (LD == 0) ? (idx ^ ((idx >> 4) & 3)) : idx;
      v[t] = s_bp[ii];                       // direct LDS.64 into pair
    }
    const int ui0 = p + ((4 * cc) << LD);
    const bool full = (tmin + ui0 >= 0) && (tmin + ui0 + (3 << LD) < NN);

    if (full) {
      // ---- hot path: no bounds checks, no per-q branching ----
#pragma unroll 1
      for (int q = 0; q < QQ; q++) {
        ull a0, a1, a2, a3;
        conv15(s_w2 + q * WSTRIDE, v, a0, a1, a2, a3);
        const float alpha = s_alpha[q];
        float* su = s_u + q * QSTRIDE;

        float r0, i0, r1, i1, r2, i2, r3, i3;
        unpack2(a0, r0, i0); unpack2(a1, r1, i1);
        unpack2(a2, r2, i2); unpack2(a3, r3, i3);
        const float h0 = fsqrt_fast(fmaf(r0, r0, i0 * i0));
        const float h1 = fsqrt_fast(fmaf(r1, r1, i1 * i1));
        const float h2 = fsqrt_fast(fmaf(r2, r2, i2 * i2));
        const float h3 = fsqrt_fast(fmaf(r3, r3, i3 * i3));
        const float u0 = fex2_fast(alpha * __log2f(h0 + beta));
        const float u1 = fex2_fast(alpha * __log2f(h1 + beta));
        const float u2 = fex2_fast(alpha * __log2f(h2 + beta));
        const float u3 = fex2_fast(alpha * __log2f(h3 + beta));
        if (LD == 0) {
          int f = ui0 >> 2; f ^= (f >> 3) & 7;
          reinterpret_cast<float4*>(su)[f] = make_float4(u0, u1, u2, u3);
        } else {
          su[swzw(ui0)]            = u0;
          su[swzw(ui0 + (1<<LD))]  = u1;
          su[swzw(ui0 + (2<<LD))]  = u2;
          su[swzw(ui0 + (3<<LD))]  = u3;
        }
      }
    } else {
      // ---- boundary path: per-element t guards (stores unconditional) ----
#pragma unroll 1
      for (int q = 0; q < QQ; q++) {
        ull a0, a1, a2, a3;
        conv15(s_w2 + q * WSTRIDE, v, a0, a1, a2, a3);
        const float alpha = s_alpha[q];
        float* su = s_u + q * QSTRIDE;
#pragma unroll
        for (int r = 0; r < 4; r++) {
          const ull av = (r == 0) ? a0 : (r == 1) ? a1 : (r == 2) ? a2 : a3;
          const int ui = ui0 + (r << LD);
          float rr, ii2; unpack2(av, rr, ii2);
          const int t = tmin + ui;
          float u = 0.f;
          if (t >= 0 && t < NN) {
            const float hyp = fsqrt_fast(fmaf(rr, rr, ii2 * ii2));
            u = fex2_fast(alpha * __log2f(hyp + beta));
          }
          su[swzw(ui)] = u;
        }
      }
    }
  }
  __syncthreads();

  // ---- down stage: packed FFMA2, consume-on-load, g pairs via LDS.128 ----
  const ulonglong2* g4 = reinterpret_cast<const ulonglong2*>(s_g2);
#pragma unroll
  for (int rep = 0; rep < 2; rep++) {
    const int w = tid + 256 * rep;
    const int q = w >> 6, g = w & 63;
    const ulonglong2* su2 = reinterpret_cast<const ulonglong2*>(s_u + q * QSTRIDE);
    ull acc[4] = {0ull, 0ull, 0ull, 0ull};
#pragma unroll
    for (int mm = 0; mm < 13; mm++) {
      int f = 4 * g + mm; f ^= (f >> 3) & 7;
      const ulonglong2 t = su2[f];
      // acc[r] += g2[2(mm-r)]*t.x + g2[2(mm-r)+1]*t.y, pair = g4[mm-r]
#pragma unroll
      for (int r = 0; r < 4; r++) {
        const int pi = mm - r;
        if (pi >= 0 && pi <= 9) {
          const ulonglong2 gp = g4[pi];
          acc[r] = ffma2(gp.x, t.x, acc[r]);
          acc[r] = ffma2(gp.y, t.y, acc[r]);
        }
      }
    }
    float4 o;
    float* op = &o.x;
#pragma unroll
    for (int r = 0; r < 4; r++) {
      float lo, hi; unpack2(acc[r], lo, hi);
      op[r] = lo + hi;
    }
    float* dst = out + ((size_t)(b * OUTCH + j * CQ + c * QQ + q)) * OUTN
                     + o0 + 4 * g;
    *reinterpret_cast<float4*>(dst) = o;
  }
}

__global__ __launch_bounds__(256, 4) void scatter_all(
    const float* __restrict__ conv_w, const float* __restrict__ roots,
    const float* __restrict__ beta_p, float* __restrict__ out)
{
  __shared__ __align__(16) ull s_bp[BPF2];
  __shared__ float  s_u[QQ * QSTRIDE];
  __shared__ __align__(16) ull s_w2[QQ * WSTRIDE];
  __shared__ __align__(16) ull s_g2[20];
  __shared__ float  s_alpha[QQ];

  const int j   = blockIdx.z;
  const int row = blockIdx.y;
  const int o0  = blockIdx.x * TOX;

  if (j <= 1)
    scatter_body<0>(s_bp, s_u, s_w2, s_g2, s_alpha, j, row, o0, conv_w, roots, beta_p, out);
  else if (j == 2)
    scatter_body<1>(s_bp, s_u, s_w2, s_g2, s_alpha, j, row, o0, conv_w, roots, beta_p, out);
  else if (j == 3)
    scatter_body<2>(s_bp, s_u, s_w2, s_g2, s_alpha, j, row, o0, conv_w, roots, beta_p, out);
  else
    scatter_body<3>(s_bp, s_u, s_w2, s_g2, s_alpha, j, row, o0, conv_w, roots, beta_p, out);
}

// ---------------- launch ----------------
extern "C" void kernel_launch(void* const* d_in, const int* in_sizes, int n_in,
                              void* d_out, int out_size)
{
  const float* x      = (const float*)d_in[0];
  const float* conv_w = (const float*)d_in[1];
  const float* roots  = (const float*)d_in[2];
  const float* beta   = (const float*)d_in[3];
  float* out = (float*)d_out;

  dim3 gW(NN / TILE_W, ROWS);                 // 64 x 16 = 1024 CTAs
  udtcwt_kernel<<<gW, 256>>>(x);

  dim3 gS(OUTN / TOX, ROWS, JLEV);            // 64 x 16 x 5 = 5120 CTAs
  scatter_all<<<gS, 256>>>(conv_w, roots, beta, out);
}